// round 12
// baseline (speedup 1.0000x reference)
#include <cuda_runtime.h>
#include <cuda_bf16.h>
#include <cuda_fp16.h>
#include <cstdint>
#include <cstddef>

#define N_TOK 2048
#define BATCH 4
#define DM    1024
#define DKV   256
#define M_TOTAL (BATCH * N_TOK)   // 8192
#define LOG2E 1.4426950408889634f
#define ONES16 0x3C003C00u        // fp16x2 {1.0, 1.0}

// ---- bf16 GEMM tiles (BK=64 -> 128B rows, SW128) ----
#define GBM 128
#define GBN 64
#define GBK 64
#define GSM_AH 0
#define GSM_AL 16384
#define GSM_BH 32768
#define GSM_BL 40960
#define GSM_TOT 49152

// ---- attention smem map (16-bit hi/lo planes, SW128, 128B rows) ----
#define QT 128
#define KT 64
#define KVSZ 32768                    // KH|KL|VH|VL, 8KB each
#define SM_QH 0
#define SM_QL 16384
#define SM_KV0 32768
#define SM_BI  (SM_KV0 + 2 * KVSZ)    // 98304
#define SM_TOT (SM_BI + 2176 * 4)     // 107008 -> 2 CTAs/SM

// ---------------- scratch ----------------
__device__ float g_Wf[768 * 1024];
__device__ float g_WoS[1024 * 256];
__device__ float g_bias[4095 * 4];
__device__ float g_O[M_TOTAL * DKV];
__device__ __nv_bfloat16 g_QH[M_TOTAL * DKV];
__device__ __nv_bfloat16 g_QL[M_TOTAL * DKV];
__device__ __nv_bfloat16 g_KH[M_TOTAL * DKV];
__device__ __nv_bfloat16 g_KL[M_TOTAL * DKV];
__device__ __half g_VH[M_TOTAL * DKV];     // fp16 planes for PV phase
__device__ __half g_VL[M_TOTAL * DKV];

// ---------------- fold weights + bias table ----------------
__global__ void fold_kernel(const float* __restrict__ Wq, const float* __restrict__ Wk,
                            const float* __restrict__ Wv, const float* __restrict__ Wo,
                            const float* __restrict__ rb) {
    int idx = blockIdx.x * blockDim.x + threadIdx.x;
    if (idx < 256 * 1024) {
        int r   = idx >> 10;
        int col = idx & 1023;
        int h = r >> 6, d = r & 63;
        float sq = 0.f, sk = 0.f, sv = 0.f;
        #pragma unroll
        for (int g = 0; g < 4; g++) {
            int src = ((g * 4 + h) * 64 + d) * 1024 + col;
            sq += Wq[src]; sk += Wk[src]; sv += Wv[src];
        }
        g_Wf[(size_t)r * 1024 + col]         = sq * LOG2E;   // log2e folded into Q
        g_Wf[(size_t)(256 + r) * 1024 + col] = sk * 0.25f;
        g_Wf[(size_t)(512 + r) * 1024 + col] = sv * 0.25f;

        int j = idx >> 8;
        int c = idx & 255;
        float so = 0.f;
        #pragma unroll
        for (int g = 0; g < 4; g++) so += Wo[j * 1024 + g * 256 + c];
        g_WoS[idx] = so;
    }
    if (idx < 4095 * 4) {
        int i = idx >> 2, h = idx & 3;
        int rel = i - 2047;
        int bucket = (rel > 0) ? 16 : 0;
        int rp = rel < 0 ? -rel : rel;
        int lb;
        if (rp < 8) lb = rp;
        else {
            int cnt = (rp >= 12) + (rp >= 16) + (rp >= 23) + (rp >= 32) +
                      (rp >= 46) + (rp >= 64) + (rp >= 91);
            lb = 8 + cnt;
        }
        bucket += lb;
        float s = 0.f;
        #pragma unroll
        for (int g = 0; g < 4; g++) s += rb[bucket * 16 + g * 4 + h];
        g_bias[idx] = s * 0.25f * LOG2E;      // log2 domain
    }
}

// ---------------- PTX helpers ----------------
#define MMA_BF16(d, a, b0, b1)                                              \
    asm volatile("mma.sync.aligned.m16n8k16.row.col.f32.bf16.bf16.f32 "     \
        "{%0,%1,%2,%3}, {%4,%5,%6,%7}, {%8,%9}, {%0,%1,%2,%3};"             \
        : "+f"(d[0]), "+f"(d[1]), "+f"(d[2]), "+f"(d[3])                    \
        : "r"(a[0]), "r"(a[1]), "r"(a[2]), "r"(a[3]), "r"(b0), "r"(b1))

#define MMA_F16(d, a, b0, b1)                                               \
    asm volatile("mma.sync.aligned.m16n8k16.row.col.f32.f16.f16.f32 "       \
        "{%0,%1,%2,%3}, {%4,%5,%6,%7}, {%8,%9}, {%0,%1,%2,%3};"             \
        : "+f"(d[0]), "+f"(d[1]), "+f"(d[2]), "+f"(d[3])                    \
        : "r"(a[0]), "r"(a[1]), "r"(a[2]), "r"(a[3]), "r"(b0), "r"(b1))

__device__ __forceinline__ void ldsm4(unsigned* r, uint32_t addr) {
    asm volatile("ldmatrix.sync.aligned.m8n8.x4.shared.b16 {%0,%1,%2,%3}, [%4];"
                 : "=r"(r[0]), "=r"(r[1]), "=r"(r[2]), "=r"(r[3]) : "r"(addr));
}
__device__ __forceinline__ void ldsm2t(unsigned& r0, unsigned& r1, uint32_t addr) {
    asm volatile("ldmatrix.sync.aligned.m8n8.x2.trans.shared.b16 {%0,%1}, [%2];"
                 : "=r"(r0), "=r"(r1) : "r"(addr));
}

// pack {e0,e1} -> bf16x2 (low half = e0)
__device__ __forceinline__ unsigned pk2(float e0, float e1) {
    unsigned r; asm("cvt.rn.bf16x2.f32 %0, %1, %2;" : "=r"(r) : "f"(e1), "f"(e0)); return r;
}
// pack {e0,e1} -> fp16x2 (low half = e0)
__device__ __forceinline__ unsigned pkh(float e0, float e1) {
    unsigned r; asm("cvt.rn.f16x2.f32 %0, %1, %2;" : "=r"(r) : "f"(e1), "f"(e0)); return r;
}

__device__ __forceinline__ uint32_t s2u(const void* p) {
    uint32_t a;
    asm("{ .reg .u64 t; cvta.to.shared.u64 t, %1; cvt.u32.u64 %0, t; }" : "=r"(a) : "l"(p));
    return a;
}

__device__ __forceinline__ void cpa16(uint32_t dst, const void* src) {
    asm volatile("cp.async.cg.shared.global [%0], [%1], 16;" :: "r"(dst), "l"(src));
}
#define CP_COMMIT() asm volatile("cp.async.commit_group;" ::: "memory")
#define CP_WAIT0()  asm volatile("cp.async.wait_group 0;" ::: "memory")

// FMA-pipe exp2 (no MUFU)
__device__ __forceinline__ float exp2p(float t) {
    t = fmaxf(t, -126.f);
    float r = rintf(t);
    float f = t - r;
    int   i = (int)r;
    float p = 1.5403530e-4f;
    p = fmaf(p, f, 1.3333558e-3f);
    p = fmaf(p, f, 9.6181291e-3f);
    p = fmaf(p, f, 5.5504109e-2f);
    p = fmaf(p, f, 2.4022651e-1f);
    p = fmaf(p, f, 6.9314718e-1f);
    p = fmaf(p, f, 1.0f);
    return p * __int_as_float((i + 127) << 23);
}

#define SWZ(x) ((x) ^ (((x) >> 3) & 0x70))

// split f32x4 into bf16 hi/lo at swizzled byte offset
__device__ __forceinline__ void split_st(char* hb, char* lb, int off, float4 v) {
    unsigned h01 = pk2(v.x, v.y), h23 = pk2(v.z, v.w);
    float rx = v.x - __uint_as_float(h01 << 16);
    float ry = v.y - __uint_as_float(h01 & 0xffff0000u);
    float rz = v.z - __uint_as_float(h23 << 16);
    float rw = v.w - __uint_as_float(h23 & 0xffff0000u);
    unsigned l01 = pk2(rx, ry), l23 = pk2(rz, rw);
    int sw = SWZ(off);
    *(uint2*)(hb + sw) = make_uint2(h01, h23);
    *(uint2*)(lb + sw) = make_uint2(l01, l23);
}

// bf16 hi/lo pair to global planes
__device__ __forceinline__ void st_pair(__nv_bfloat16* H, __nv_bfloat16* L,
                                        size_t off, float a, float b) {
    unsigned hp = pk2(a, b);
    unsigned lp = pk2(a - __uint_as_float(hp << 16),
                      b - __uint_as_float(hp & 0xffff0000u));
    *(unsigned*)(H + off) = hp;
    *(unsigned*)(L + off) = lp;
}
// fp16 hi/lo pair to global planes
__device__ __forceinline__ void st_pair_h(__half* H, __half* L,
                                          size_t off, float a, float b) {
    unsigned hp = pkh(a, b);
    float ha = __half2float(__ushort_as_half((unsigned short)(hp & 0xffffu)));
    float hb = __half2float(__ushort_as_half((unsigned short)(hp >> 16)));
    unsigned lp = pkh(a - ha, b - hb);
    *(unsigned*)(H + off) = hp;
    *(unsigned*)(L + off) = lp;
}

// ---------------- bf16 hi/lo 3-term GEMM ----------------
// mode 0: C f32. mode 1: QKV epilogue -> Q/K bf16 planes, V fp16 planes.
__global__ __launch_bounds__(256, 2)
void gemm_bf16(const float* __restrict__ A, const float* __restrict__ B,
               float* __restrict__ C, int M, int N, int K, int mode) {
    extern __shared__ char smem[];
    uint32_t sb = s2u(smem);

    int tid  = threadIdx.x;
    int lane = tid & 31, warp = tid >> 5;
    int wm = warp >> 1, wn = warp & 1;
    int gid = lane >> 2, tig = lane & 3;
    int q8 = lane >> 3, r8 = lane & 7;
    int m0 = blockIdx.y * GBM, n0 = blockIdx.x * GBN;

    float acc[2][4][4];
    #pragma unroll
    for (int mi = 0; mi < 2; mi++)
        #pragma unroll
        for (int ni = 0; ni < 4; ni++)
            #pragma unroll
            for (int r = 0; r < 4; r++) acc[mi][ni][r] = 0.f;

    for (int kt = 0; kt < K; kt += GBK) {
        __syncthreads();
        #pragma unroll
        for (int p = 0; p < 8; p++) {
            int f = tid + p * 256;
            int row = f >> 4, seg = (f & 15) * 4;
            float4 v = *(const float4*)(A + (size_t)(m0 + row) * K + kt + seg);
            split_st(smem + GSM_AH, smem + GSM_AL, row * 128 + seg * 2, v);
        }
        #pragma unroll
        for (int p = 0; p < 4; p++) {
            int f = tid + p * 256;
            int row = f >> 4, seg = (f & 15) * 4;
            float4 v = *(const float4*)(B + (size_t)(n0 + row) * K + kt + seg);
            split_st(smem + GSM_BH, smem + GSM_BL, row * 128 + seg * 2, v);
        }
        __syncthreads();

        #pragma unroll
        for (int kb = 0; kb < 4; kb++) {
            unsigned ah[2][4], al[2][4];
            #pragma unroll
            for (int mi = 0; mi < 2; mi++) {
                int ao = (wm * 32 + mi * 16 + ((q8 & 1) ? 8 : 0) + r8) * 128
                       + ((q8 & 2) ? 16 : 0) + kb * 32;
                ldsm4(ah[mi], sb + GSM_AH + SWZ(ao));
                ldsm4(al[mi], sb + GSM_AL + SWZ(ao));
            }
            #pragma unroll
            for (int ng = 0; ng < 2; ng++) {
                unsigned bh[4], bl[4];
                int bo = (wn * 32 + ng * 16 + ((q8 & 2) ? 8 : 0) + r8) * 128
                       + ((q8 & 1) ? 16 : 0) + kb * 32;
                ldsm4(bh, sb + GSM_BH + SWZ(bo));
                ldsm4(bl, sb + GSM_BL + SWZ(bo));
                #pragma unroll
                for (int mi = 0; mi < 2; mi++) {
                    MMA_BF16(acc[mi][2 * ng],     ah[mi], bh[0], bh[1]);
                    MMA_BF16(acc[mi][2 * ng],     al[mi], bh[0], bh[1]);
                    MMA_BF16(acc[mi][2 * ng],     ah[mi], bl[0], bl[1]);
                    MMA_BF16(acc[mi][2 * ng + 1], ah[mi], bh[2], bh[3]);
                    MMA_BF16(acc[mi][2 * ng + 1], al[mi], bh[2], bh[3]);
                    MMA_BF16(acc[mi][2 * ng + 1], ah[mi], bl[2], bl[3]);
                }
            }
        }
    }

    #pragma unroll
    for (int mi = 0; mi < 2; mi++) {
        #pragma unroll
        for (int ni = 0; ni < 4; ni++) {
            int row0 = m0 + wm * 32 + mi * 16 + gid;
            int ncol = n0 + wn * 32 + ni * 8 + tig * 2;
            float* a4 = acc[mi][ni];
            if (mode == 0) {
                *(float2*)(C + (size_t)row0 * N + ncol)       = make_float2(a4[0], a4[1]);
                *(float2*)(C + (size_t)(row0 + 8) * N + ncol) = make_float2(a4[2], a4[3]);
            } else {
                int buf = ncol >> 8, rem = ncol & 255;
                size_t o0 = (size_t)row0 * DKV + rem;
                size_t o1 = (size_t)(row0 + 8) * DKV + rem;
                if (buf == 0) {
                    st_pair(g_QH, g_QL, o0, a4[0], a4[1]);
                    st_pair(g_QH, g_QL, o1, a4[2], a4[3]);
                } else if (buf == 1) {
                    st_pair(g_KH, g_KL, o0, a4[0], a4[1]);
                    st_pair(g_KH, g_KL, o1, a4[2], a4[3]);
                } else {
                    st_pair_h(g_VH, g_VL, o0, a4[0], a4[1]);
                    st_pair_h(g_VH, g_VL, o1, a4[2], a4[3]);
                }
            }
        }
    }
}

// ---------------- KV tile prefetch (cp.async, 16B chunks) ----------------
__device__ __forceinline__ void prefetch_kv(
    uint32_t kvb, const __nv_bfloat16* KH, const __nv_bfloat16* KL,
    const __half* VH, const __half* VL, int kv0, int tid) {
    #pragma unroll
    for (int p = 0; p < 2; p++) {
        int f = tid + p * 256;            // 64 rows x 8 chunks
        int row = f >> 3, c8 = f & 7;
        size_t go = (size_t)(kv0 + row) * DKV + c8 * 8;
        int so = SWZ(row * 128 + c8 * 16);
        cpa16(kvb + so,         KH + go);
        cpa16(kvb + 8192 + so,  KL + go);
        cpa16(kvb + 16384 + so, VH + go);
        cpa16(kvb + 24576 + so, VL + go);
    }
}

// ---------------- flash attention: bf16 3-term S, fp16 single-P PV ----------------
__global__ __launch_bounds__(256, 2)
void attn_mma() {
    extern __shared__ char smem[];
    uint32_t sb = s2u(smem);
    int tid = threadIdx.x;
    int lane = tid & 31, w = tid >> 5;
    int gid = lane >> 2, tig = lane & 3;
    int wrow = w * 16;
    int q0 = blockIdx.x * QT;
    int bh = blockIdx.y;
    int b = bh >> 2, h = bh & 3;

    float* biass = (float*)(smem + SM_BI);
    for (int i = tid; i < 2176; i += 256) {
        int t = i - 127 - q0 + 2047;
        t = max(0, min(4094, t));
        biass[i] = g_bias[t * 4 + h];
    }

    size_t base = (size_t)(b * N_TOK) * DKV + h * 64;
    const __nv_bfloat16* QHg = g_QH + base + (size_t)q0 * DKV;
    const __nv_bfloat16* QLg = g_QL + base + (size_t)q0 * DKV;
    const __nv_bfloat16* KHg = g_KH + base;
    const __nv_bfloat16* KLg = g_KL + base;
    const __half* VHg = g_VH + base;
    const __half* VLg = g_VL + base;

    #pragma unroll
    for (int p = 0; p < 4; p++) {
        int f = tid + p * 256;
        int row = f >> 3, c8 = f & 7;
        size_t go = (size_t)row * DKV + c8 * 8;
        int so = SWZ(row * 128 + c8 * 16);
        cpa16(sb + SM_QH + so, QHg + go);
        cpa16(sb + SM_QL + so, QLg + go);
    }
    prefetch_kv(sb + SM_KV0, KHg, KLg, VHg, VLg, 0, tid);
    CP_COMMIT();

    int mi = lane >> 3, r8 = lane & 7;
    int aoff = (wrow + ((mi & 1) ? 8 : 0) + r8) * 128 + ((mi & 2) ? 16 : 0);
    int boff = (((mi & 2) ? 8 : 0) + r8) * 128 + ((mi & 1) ? 16 : 0);
    int voff = (lane & 15) * 128;

    float m0r = -1e30f, m1r = -1e30f, l0r = 0.f, l1r = 0.f;
    float o[8][4];
    #pragma unroll
    for (int ni = 0; ni < 8; ni++)
        #pragma unroll
        for (int q = 0; q < 4; q++) o[ni][q] = 0.f;

    for (int kv0 = 0, t = 0; kv0 < N_TOK; kv0 += KT, t++) {
        CP_WAIT0();
        __syncthreads();
        if (kv0 + KT < N_TOK) {
            prefetch_kv(sb + SM_KV0 + ((t + 1) & 1) * KVSZ,
                        KHg, KLg, VHg, VLg, kv0 + KT, tid);
            CP_COMMIT();
        }
        uint32_t kvb = sb + SM_KV0 + (t & 1) * KVSZ;

        // ---- S = Q K^T (bf16 3-term hi/lo) ----
        float s[8][4];
        #pragma unroll
        for (int ni = 0; ni < 8; ni++)
            #pragma unroll
            for (int q = 0; q < 4; q++) s[ni][q] = 0.f;

        #pragma unroll
        for (int ks = 0; ks < 4; ks++) {
            unsigned qh[4], ql[4];
            ldsm4(qh, sb + SM_QH + SWZ(aoff + ks * 32));
            ldsm4(ql, sb + SM_QL + SWZ(aoff + ks * 32));
            #pragma unroll
            for (int np = 0; np < 4; np++) {
                unsigned kh[4], kl[4];
                int bo = boff + np * 2048 + ks * 32;
                ldsm4(kh, kvb + SWZ(bo));
                ldsm4(kl, kvb + 8192 + SWZ(bo));
                MMA_BF16(s[2 * np],     qh, kh[0], kh[1]);
                MMA_BF16(s[2 * np],     ql, kh[0], kh[1]);
                MMA_BF16(s[2 * np],     qh, kl[0], kl[1]);
                MMA_BF16(s[2 * np + 1], qh, kh[2], kh[3]);
                MMA_BF16(s[2 * np + 1], ql, kh[2], kh[3]);
                MMA_BF16(s[2 * np + 1], qh, kl[2], kl[3]);
            }
        }

        // ---- bias add ----
        const float* bp0 = biass + (kv0 + 127 - wrow - gid);
        #pragma unroll
        for (int ni = 0; ni < 8; ni++) {
            int c = ni * 8 + 2 * tig;
            s[ni][0] += bp0[c];
            s[ni][1] += bp0[c + 1];
            s[ni][2] += bp0[c - 8];
            s[ni][3] += bp0[c - 7];
        }

        // ---- online softmax (log2 domain); row-sum comes from ones-MMA below ----
        float mx0 = -1e30f, mx1 = -1e30f;
        #pragma unroll
        for (int ni = 0; ni < 8; ni++) {
            mx0 = fmaxf(mx0, fmaxf(s[ni][0], s[ni][1]));
            mx1 = fmaxf(mx1, fmaxf(s[ni][2], s[ni][3]));
        }
        mx0 = fmaxf(mx0, __shfl_xor_sync(0xffffffffu, mx0, 1));
        mx0 = fmaxf(mx0, __shfl_xor_sync(0xffffffffu, mx0, 2));
        mx1 = fmaxf(mx1, __shfl_xor_sync(0xffffffffu, mx1, 1));
        mx1 = fmaxf(mx1, __shfl_xor_sync(0xffffffffu, mx1, 2));
        float mn0 = fmaxf(m0r, mx0), mn1 = fmaxf(m1r, mx1);
        float a0 = exp2p(m0r - mn0), a1 = exp2p(m1r - mn1);
        m0r = mn0; m1r = mn1;

        #pragma unroll
        for (int ni = 0; ni < 8; ni++) {
            s[ni][0] = exp2p(s[ni][0] - mn0);
            s[ni][1] = exp2p(s[ni][1] - mn0);
            s[ni][2] = exp2p(s[ni][2] - mn1);
            s[ni][3] = exp2p(s[ni][3] - mn1);
        }

        #pragma unroll
        for (int ni = 0; ni < 8; ni++) {
            o[ni][0] *= a0; o[ni][1] *= a0;
            o[ni][2] *= a1; o[ni][3] *= a1;
        }

        // ---- O += P V (fp16 P, fp16 V hi/lo 2-term); l via ones-MMA ----
        float lacc[4] = {0.f, 0.f, 0.f, 0.f};
        #pragma unroll
        for (int kk = 0; kk < 4; kk++) {
            unsigned pa[4];
            pa[0] = pkh(s[2 * kk][0],     s[2 * kk][1]);
            pa[1] = pkh(s[2 * kk][2],     s[2 * kk][3]);
            pa[2] = pkh(s[2 * kk + 1][0], s[2 * kk + 1][1]);
            pa[3] = pkh(s[2 * kk + 1][2], s[2 * kk + 1][3]);
            MMA_F16(lacc, pa, ONES16, ONES16);    // row sums (all cols equal)
            #pragma unroll
            for (int ni = 0; ni < 8; ni++) {
                unsigned vh0, vh1, vl0, vl1;
                int vo = voff + kk * 2048 + ni * 16;
                ldsm2t(vh0, vh1, kvb + 16384 + SWZ(vo));
                ldsm2t(vl0, vl1, kvb + 24576 + SWZ(vo));
                MMA_F16(o[ni], pa, vh0, vh1);
                MMA_F16(o[ni], pa, vl0, vl1);
            }
        }
        l0r = l0r * a0 + lacc[0];
        l1r = l1r * a1 + lacc[2];
    }

    // epilogue
    float inv0 = 1.f / l0r, inv1 = 1.f / l1r;
    float* Og = g_O + ((size_t)(b * N_TOK + q0 + wrow + gid)) * DKV + h * 64;
    #pragma unroll
    for (int ni = 0; ni < 8; ni++) {
        int c = ni * 8 + 2 * tig;
        *(float2*)(Og + c)           = make_float2(o[ni][0] * inv0, o[ni][1] * inv0);
        *(float2*)(Og + 8 * DKV + c) = make_float2(o[ni][2] * inv1, o[ni][3] * inv1);
    }
}

// ---------------- launch ----------------
extern "C" void kernel_launch(void* const* d_in, const int* in_sizes, int n_in,
                              void* d_out, int out_size) {
    const float* hs = (const float*)d_in[0];
    const float* Wq = (const float*)d_in[1];
    const float* Wk = (const float*)d_in[2];
    const float* Wv = (const float*)d_in[3];
    const float* Wo = (const float*)d_in[4];
    const float* rb = (const float*)d_in[5];
    float* out = (float*)d_out;

    void *pWf, *pWoS, *pO;
    cudaGetSymbolAddress(&pWf, g_Wf);
    cudaGetSymbolAddress(&pWoS, g_WoS);
    cudaGetSymbolAddress(&pO, g_O);

    fold_kernel<<<1024, 256>>>(Wq, Wk, Wv, Wo, rb);

    cudaFuncSetAttribute(gemm_bf16, cudaFuncAttributeMaxDynamicSharedMemorySize, GSM_TOT);
    gemm_bf16<<<dim3(768 / GBN, M_TOTAL / GBM), 256, GSM_TOT>>>(
        hs, (const float*)pWf, nullptr, M_TOTAL, 768, DM, 1);

    cudaFuncSetAttribute(attn_mma, cudaFuncAttributeMaxDynamicSharedMemorySize, SM_TOT);
    attn_mma<<<dim3(N_TOK / QT, BATCH * 4), 256, SM_TOT>>>();

    gemm_bf16<<<dim3(DM / GBN, M_TOTAL / GBM), 256, GSM_TOT>>>(
        (const float*)pO, (const float*)pWoS, out, M_TOTAL, DM, DKV, 0);
}

// round 13
// speedup vs baseline: 1.6177x; 1.6177x over previous
#include <cuda_runtime.h>
#include <cuda_bf16.h>
#include <cuda_fp16.h>
#include <cstdint>
#include <cstddef>

#define N_TOK 2048
#define BATCH 4
#define DM    1024
#define DKV   256
#define M_TOTAL (BATCH * N_TOK)   // 8192
#define LOG2E 1.4426950408889634f
#define ONES16 0x3C003C00u        // fp16x2 {1.0, 1.0}

// ---- bf16 GEMM tiles (BK=64 -> 128B rows, SW128) ----
#define GBM 128
#define GBN 64
#define GBK 64
#define GSM_AH 0
#define GSM_AL 16384
#define GSM_BH 32768
#define GSM_BL 40960
#define GSM_TOT 49152

// ---- attention smem map (KH|KL bf16, VH fp16; SW128, 128B rows) ----
#define QT 128
#define KT 64
#define KVSZ 24576                    // KH 8K | KL 8K | VH 8K
#define SM_QH 0
#define SM_QL 16384
#define SM_KV0 32768
#define SM_BI  (SM_KV0 + 2 * KVSZ)    // 81920
#define SM_TOT (SM_BI + 2176 * 4)     // 90624 -> 2 CTAs/SM

// ---------------- scratch ----------------
__device__ float g_Wf[768 * 1024];
__device__ float g_WoS[1024 * 256];
__device__ float g_bias[4095 * 4];
__device__ float g_O[M_TOTAL * DKV];
__device__ __nv_bfloat16 g_QH[M_TOTAL * DKV];
__device__ __nv_bfloat16 g_QL[M_TOTAL * DKV];
__device__ __nv_bfloat16 g_KH[M_TOTAL * DKV];
__device__ __nv_bfloat16 g_KL[M_TOTAL * DKV];
__device__ __half g_VH[M_TOTAL * DKV];     // single fp16 V plane

// ---------------- fold weights + bias table ----------------
__global__ void fold_kernel(const float* __restrict__ Wq, const float* __restrict__ Wk,
                            const float* __restrict__ Wv, const float* __restrict__ Wo,
                            const float* __restrict__ rb) {
    int idx = blockIdx.x * blockDim.x + threadIdx.x;
    if (idx < 256 * 1024) {
        int r   = idx >> 10;
        int col = idx & 1023;
        int h = r >> 6, d = r & 63;
        float sq = 0.f, sk = 0.f, sv = 0.f;
        #pragma unroll
        for (int g = 0; g < 4; g++) {
            int src = ((g * 4 + h) * 64 + d) * 1024 + col;
            sq += Wq[src]; sk += Wk[src]; sv += Wv[src];
        }
        g_Wf[(size_t)r * 1024 + col]         = sq * LOG2E;   // log2e folded into Q
        g_Wf[(size_t)(256 + r) * 1024 + col] = sk * 0.25f;
        g_Wf[(size_t)(512 + r) * 1024 + col] = sv * 0.25f;

        int j = idx >> 8;
        int c = idx & 255;
        float so = 0.f;
        #pragma unroll
        for (int g = 0; g < 4; g++) so += Wo[j * 1024 + g * 256 + c];
        g_WoS[idx] = so;
    }
    if (idx < 4095 * 4) {
        int i = idx >> 2, h = idx & 3;
        int rel = i - 2047;
        int bucket = (rel > 0) ? 16 : 0;
        int rp = rel < 0 ? -rel : rel;
        int lb;
        if (rp < 8) lb = rp;
        else {
            int cnt = (rp >= 12) + (rp >= 16) + (rp >= 23) + (rp >= 32) +
                      (rp >= 46) + (rp >= 64) + (rp >= 91);
            lb = 8 + cnt;
        }
        bucket += lb;
        float s = 0.f;
        #pragma unroll
        for (int g = 0; g < 4; g++) s += rb[bucket * 16 + g * 4 + h];
        g_bias[idx] = s * 0.25f * LOG2E;      // log2 domain
    }
}

// ---------------- PTX helpers ----------------
#define MMA_BF16(d, a, b0, b1)                                              \
    asm volatile("mma.sync.aligned.m16n8k16.row.col.f32.bf16.bf16.f32 "     \
        "{%0,%1,%2,%3}, {%4,%5,%6,%7}, {%8,%9}, {%0,%1,%2,%3};"             \
        : "+f"(d[0]), "+f"(d[1]), "+f"(d[2]), "+f"(d[3])                    \
        : "r"(a[0]), "r"(a[1]), "r"(a[2]), "r"(a[3]), "r"(b0), "r"(b1))

#define MMA_F16(d, a, b0, b1)                                               \
    asm volatile("mma.sync.aligned.m16n8k16.row.col.f32.f16.f16.f32 "       \
        "{%0,%1,%2,%3}, {%4,%5,%6,%7}, {%8,%9}, {%0,%1,%2,%3};"             \
        : "+f"(d[0]), "+f"(d[1]), "+f"(d[2]), "+f"(d[3])                    \
        : "r"(a[0]), "r"(a[1]), "r"(a[2]), "r"(a[3]), "r"(b0), "r"(b1))

__device__ __forceinline__ void ldsm4(unsigned* r, uint32_t addr) {
    asm volatile("ldmatrix.sync.aligned.m8n8.x4.shared.b16 {%0,%1,%2,%3}, [%4];"
                 : "=r"(r[0]), "=r"(r[1]), "=r"(r[2]), "=r"(r[3]) : "r"(addr));
}
__device__ __forceinline__ void ldsm4t(unsigned* r, uint32_t addr) {
    asm volatile("ldmatrix.sync.aligned.m8n8.x4.trans.shared.b16 {%0,%1,%2,%3}, [%4];"
                 : "=r"(r[0]), "=r"(r[1]), "=r"(r[2]), "=r"(r[3]) : "r"(addr));
}

// pack {e0,e1} -> bf16x2 (low half = e0)
__device__ __forceinline__ unsigned pk2(float e0, float e1) {
    unsigned r; asm("cvt.rn.bf16x2.f32 %0, %1, %2;" : "=r"(r) : "f"(e1), "f"(e0)); return r;
}
// pack {e0,e1} -> fp16x2 (low half = e0)
__device__ __forceinline__ unsigned pkh(float e0, float e1) {
    unsigned r; asm("cvt.rn.f16x2.f32 %0, %1, %2;" : "=r"(r) : "f"(e1), "f"(e0)); return r;
}

__device__ __forceinline__ uint32_t s2u(const void* p) {
    uint32_t a;
    asm("{ .reg .u64 t; cvta.to.shared.u64 t, %1; cvt.u32.u64 %0, t; }" : "=r"(a) : "l"(p));
    return a;
}

__device__ __forceinline__ void cpa16(uint32_t dst, const void* src) {
    asm volatile("cp.async.cg.shared.global [%0], [%1], 16;" :: "r"(dst), "l"(src));
}
#define CP_COMMIT() asm volatile("cp.async.commit_group;" ::: "memory")
#define CP_WAIT0()  asm volatile("cp.async.wait_group 0;" ::: "memory")

// FMA-pipe exp2 (no MUFU), degree-5 (tail error ~2.4e-6)
__device__ __forceinline__ float exp2p(float t) {
    t = fmaxf(t, -126.f);
    float r = rintf(t);
    float f = t - r;
    int   i = (int)r;
    float p = 1.3333558e-3f;
    p = fmaf(p, f, 9.6181291e-3f);
    p = fmaf(p, f, 5.5504109e-2f);
    p = fmaf(p, f, 2.4022651e-1f);
    p = fmaf(p, f, 6.9314718e-1f);
    p = fmaf(p, f, 1.0f);
    return p * __int_as_float((i + 127) << 23);
}

#define SWZ(x) ((x) ^ (((x) >> 3) & 0x70))

// split f32x4 into bf16 hi/lo at swizzled byte offset
__device__ __forceinline__ void split_st(char* hb, char* lb, int off, float4 v) {
    unsigned h01 = pk2(v.x, v.y), h23 = pk2(v.z, v.w);
    float rx = v.x - __uint_as_float(h01 << 16);
    float ry = v.y - __uint_as_float(h01 & 0xffff0000u);
    float rz = v.z - __uint_as_float(h23 << 16);
    float rw = v.w - __uint_as_float(h23 & 0xffff0000u);
    unsigned l01 = pk2(rx, ry), l23 = pk2(rz, rw);
    int sw = SWZ(off);
    *(uint2*)(hb + sw) = make_uint2(h01, h23);
    *(uint2*)(lb + sw) = make_uint2(l01, l23);
}

// bf16 hi/lo pair to global planes
__device__ __forceinline__ void st_pair(__nv_bfloat16* H, __nv_bfloat16* L,
                                        size_t off, float a, float b) {
    unsigned hp = pk2(a, b);
    unsigned lp = pk2(a - __uint_as_float(hp << 16),
                      b - __uint_as_float(hp & 0xffff0000u));
    *(unsigned*)(H + off) = hp;
    *(unsigned*)(L + off) = lp;
}

// ---------------- bf16 hi/lo 3-term GEMM ----------------
// mode 0: C f32. mode 1: QKV epilogue -> Q/K bf16 hi/lo planes, V single fp16 plane.
__global__ __launch_bounds__(256, 2)
void gemm_bf16(const float* __restrict__ A, const float* __restrict__ B,
               float* __restrict__ C, int M, int N, int K, int mode) {
    extern __shared__ char smem[];
    uint32_t sb = s2u(smem);

    int tid  = threadIdx.x;
    int lane = tid & 31, warp = tid >> 5;
    int wm = warp >> 1, wn = warp & 1;
    int gid = lane >> 2, tig = lane & 3;
    int q8 = lane >> 3, r8 = lane & 7;
    int m0 = blockIdx.y * GBM, n0 = blockIdx.x * GBN;

    float acc[2][4][4];
    #pragma unroll
    for (int mi = 0; mi < 2; mi++)
        #pragma unroll
        for (int ni = 0; ni < 4; ni++)
            #pragma unroll
            for (int r = 0; r < 4; r++) acc[mi][ni][r] = 0.f;

    for (int kt = 0; kt < K; kt += GBK) {
        __syncthreads();
        #pragma unroll
        for (int p = 0; p < 8; p++) {
            int f = tid + p * 256;
            int row = f >> 4, seg = (f & 15) * 4;
            float4 v = *(const float4*)(A + (size_t)(m0 + row) * K + kt + seg);
            split_st(smem + GSM_AH, smem + GSM_AL, row * 128 + seg * 2, v);
        }
        #pragma unroll
        for (int p = 0; p < 4; p++) {
            int f = tid + p * 256;
            int row = f >> 4, seg = (f & 15) * 4;
            float4 v = *(const float4*)(B + (size_t)(n0 + row) * K + kt + seg);
            split_st(smem + GSM_BH, smem + GSM_BL, row * 128 + seg * 2, v);
        }
        __syncthreads();

        #pragma unroll
        for (int kb = 0; kb < 4; kb++) {
            unsigned ah[2][4], al[2][4];
            #pragma unroll
            for (int mi = 0; mi < 2; mi++) {
                int ao = (wm * 32 + mi * 16 + ((q8 & 1) ? 8 : 0) + r8) * 128
                       + ((q8 & 2) ? 16 : 0) + kb * 32;
                ldsm4(ah[mi], sb + GSM_AH + SWZ(ao));
                ldsm4(al[mi], sb + GSM_AL + SWZ(ao));
            }
            #pragma unroll
            for (int ng = 0; ng < 2; ng++) {
                unsigned bh[4], bl[4];
                int bo = (wn * 32 + ng * 16 + ((q8 & 2) ? 8 : 0) + r8) * 128
                       + ((q8 & 1) ? 16 : 0) + kb * 32;
                ldsm4(bh, sb + GSM_BH + SWZ(bo));
                ldsm4(bl, sb + GSM_BL + SWZ(bo));
                #pragma unroll
                for (int mi = 0; mi < 2; mi++) {
                    MMA_BF16(acc[mi][2 * ng],     ah[mi], bh[0], bh[1]);
                    MMA_BF16(acc[mi][2 * ng],     al[mi], bh[0], bh[1]);
                    MMA_BF16(acc[mi][2 * ng],     ah[mi], bl[0], bl[1]);
                    MMA_BF16(acc[mi][2 * ng + 1], ah[mi], bh[2], bh[3]);
                    MMA_BF16(acc[mi][2 * ng + 1], al[mi], bh[2], bh[3]);
                    MMA_BF16(acc[mi][2 * ng + 1], ah[mi], bl[2], bl[3]);
                }
            }
        }
    }

    #pragma unroll
    for (int mi = 0; mi < 2; mi++) {
        #pragma unroll
        for (int ni = 0; ni < 4; ni++) {
            int row0 = m0 + wm * 32 + mi * 16 + gid;
            int ncol = n0 + wn * 32 + ni * 8 + tig * 2;
            float* a4 = acc[mi][ni];
            if (mode == 0) {
                *(float2*)(C + (size_t)row0 * N + ncol)       = make_float2(a4[0], a4[1]);
                *(float2*)(C + (size_t)(row0 + 8) * N + ncol) = make_float2(a4[2], a4[3]);
            } else {
                int buf = ncol >> 8, rem = ncol & 255;
                size_t o0 = (size_t)row0 * DKV + rem;
                size_t o1 = (size_t)(row0 + 8) * DKV + rem;
                if (buf == 0) {
                    st_pair(g_QH, g_QL, o0, a4[0], a4[1]);
                    st_pair(g_QH, g_QL, o1, a4[2], a4[3]);
                } else if (buf == 1) {
                    st_pair(g_KH, g_KL, o0, a4[0], a4[1]);
                    st_pair(g_KH, g_KL, o1, a4[2], a4[3]);
                } else {
                    *(unsigned*)(g_VH + o0) = pkh(a4[0], a4[1]);
                    *(unsigned*)(g_VH + o1) = pkh(a4[2], a4[3]);
                }
            }
        }
    }
}

// ---------------- KV tile prefetch (cp.async, 3 planes) ----------------
__device__ __forceinline__ void prefetch_kv(
    uint32_t kvb, const __nv_bfloat16* KH, const __nv_bfloat16* KL,
    const __half* VH, int kv0, int tid) {
    #pragma unroll
    for (int p = 0; p < 2; p++) {
        int f = tid + p * 256;            // 64 rows x 8 chunks
        int row = f >> 3, c8 = f & 7;
        size_t go = (size_t)(kv0 + row) * DKV + c8 * 8;
        int so = SWZ(row * 128 + c8 * 16);
        cpa16(kvb + so,         KH + go);
        cpa16(kvb + 8192 + so,  KL + go);
        cpa16(kvb + 16384 + so, VH + go);
    }
}

// ---------------- flash attention: bf16 3-term S, fp16 P*V single-term ----------------
__global__ __launch_bounds__(256, 2)
void attn_mma() {
    extern __shared__ char smem[];
    uint32_t sb = s2u(smem);
    int tid = threadIdx.x;
    int lane = tid & 31, w = tid >> 5;
    int gid = lane >> 2, tig = lane & 3;
    int wrow = w * 16;
    int q0 = blockIdx.x * QT;
    int bh = blockIdx.y;
    int b = bh >> 2, h = bh & 3;

    float* biass = (float*)(smem + SM_BI);
    for (int i = tid; i < 2176; i += 256) {
        int t = i - 127 - q0 + 2047;
        t = max(0, min(4094, t));
        biass[i] = g_bias[t * 4 + h];
    }

    size_t base = (size_t)(b * N_TOK) * DKV + h * 64;
    const __nv_bfloat16* QHg = g_QH + base + (size_t)q0 * DKV;
    const __nv_bfloat16* QLg = g_QL + base + (size_t)q0 * DKV;
    const __nv_bfloat16* KHg = g_KH + base;
    const __nv_bfloat16* KLg = g_KL + base;
    const __half* VHg = g_VH + base;

    #pragma unroll
    for (int p = 0; p < 4; p++) {
        int f = tid + p * 256;
        int row = f >> 3, c8 = f & 7;
        size_t go = (size_t)row * DKV + c8 * 8;
        int so = SWZ(row * 128 + c8 * 16);
        cpa16(sb + SM_QH + so, QHg + go);
        cpa16(sb + SM_QL + so, QLg + go);
    }
    prefetch_kv(sb + SM_KV0, KHg, KLg, VHg, 0, tid);
    CP_COMMIT();

    int mi = lane >> 3, r8 = lane & 7;
    int aoff = (wrow + ((mi & 1) ? 8 : 0) + r8) * 128 + ((mi & 2) ? 16 : 0);
    int boff = (((mi & 2) ? 8 : 0) + r8) * 128 + ((mi & 1) ? 16 : 0);
    int voff4 = (lane & 15) * 128 + (lane >> 4) * 16;   // x4.trans: m2/m3 = +16B dcols

    float m0r = -1e30f, m1r = -1e30f, l0r = 0.f, l1r = 0.f;
    float o[8][4];
    #pragma unroll
    for (int ni = 0; ni < 8; ni++)
        #pragma unroll
        for (int q = 0; q < 4; q++) o[ni][q] = 0.f;

    for (int kv0 = 0, t = 0; kv0 < N_TOK; kv0 += KT, t++) {
        CP_WAIT0();
        __syncthreads();
        if (kv0 + KT < N_TOK) {
            prefetch_kv(sb + SM_KV0 + ((t + 1) & 1) * KVSZ,
                        KHg, KLg, VHg, kv0 + KT, tid);
            CP_COMMIT();
        }
        uint32_t kvb = sb + SM_KV0 + (t & 1) * KVSZ;

        // ---- S = Q K^T (bf16 3-term hi/lo) ----
        float s[8][4];
        #pragma unroll
        for (int ni = 0; ni < 8; ni++)
            #pragma unroll
            for (int q = 0; q < 4; q++) s[ni][q] = 0.f;

        #pragma unroll
        for (int ks = 0; ks < 4; ks++) {
            unsigned qh[4], ql[4];
            ldsm4(qh, sb + SM_QH + SWZ(aoff + ks * 32));
            ldsm4(ql, sb + SM_QL + SWZ(aoff + ks * 32));
            #pragma unroll
            for (int np = 0; np < 4; np++) {
                unsigned kh[4], kl[4];
                int bo = boff + np * 2048 + ks * 32;
                ldsm4(kh, kvb + SWZ(bo));
                ldsm4(kl, kvb + 8192 + SWZ(bo));
                MMA_BF16(s[2 * np],     qh, kh[0], kh[1]);
                MMA_BF16(s[2 * np],     ql, kh[0], kh[1]);
                MMA_BF16(s[2 * np],     qh, kl[0], kl[1]);
                MMA_BF16(s[2 * np + 1], qh, kh[2], kh[3]);
                MMA_BF16(s[2 * np + 1], ql, kh[2], kh[3]);
                MMA_BF16(s[2 * np + 1], qh, kl[2], kl[3]);
            }
        }

        // ---- bias add ----
        const float* bp0 = biass + (kv0 + 127 - wrow - gid);
        #pragma unroll
        for (int ni = 0; ni < 8; ni++) {
            int c = ni * 8 + 2 * tig;
            s[ni][0] += bp0[c];
            s[ni][1] += bp0[c + 1];
            s[ni][2] += bp0[c - 8];
            s[ni][3] += bp0[c - 7];
        }

        // ---- online softmax (log2 domain); row-sum via ones-MMA ----
        float mx0 = -1e30f, mx1 = -1e30f;
        #pragma unroll
        for (int ni = 0; ni < 8; ni++) {
            mx0 = fmaxf(mx0, fmaxf(s[ni][0], s[ni][1]));
            mx1 = fmaxf(mx1, fmaxf(s[ni][2], s[ni][3]));
        }
        mx0 = fmaxf(mx0, __shfl_xor_sync(0xffffffffu, mx0, 1));
        mx0 = fmaxf(mx0, __shfl_xor_sync(0xffffffffu, mx0, 2));
        mx1 = fmaxf(mx1, __shfl_xor_sync(0xffffffffu, mx1, 1));
        mx1 = fmaxf(mx1, __shfl_xor_sync(0xffffffffu, mx1, 2));
        float mn0 = fmaxf(m0r, mx0), mn1 = fmaxf(m1r, mx1);
        float a0 = exp2p(m0r - mn0), a1 = exp2p(m1r - mn1);
        m0r = mn0; m1r = mn1;

        #pragma unroll
        for (int ni = 0; ni < 8; ni++) {
            s[ni][0] = exp2p(s[ni][0] - mn0);
            s[ni][1] = exp2p(s[ni][1] - mn0);
            s[ni][2] = exp2p(s[ni][2] - mn1);
            s[ni][3] = exp2p(s[ni][3] - mn1);
        }

        #pragma unroll
        for (int ni = 0; ni < 8; ni++) {
            o[ni][0] *= a0; o[ni][1] *= a0;
            o[ni][2] *= a1; o[ni][3] *= a1;
        }

        // ---- O += P V (fp16 P, single fp16 V); l via ones-MMA ----
        float lacc[4] = {0.f, 0.f, 0.f, 0.f};
        #pragma unroll
        for (int kk = 0; kk < 4; kk++) {
            unsigned pa[4];
            pa[0] = pkh(s[2 * kk][0],     s[2 * kk][1]);
            pa[1] = pkh(s[2 * kk][2],     s[2 * kk][3]);
            pa[2] = pkh(s[2 * kk + 1][0], s[2 * kk + 1][1]);
            pa[3] = pkh(s[2 * kk + 1][2], s[2 * kk + 1][3]);
            MMA_F16(lacc, pa, ONES16, ONES16);    // row sums of fp16 P
            #pragma unroll
            for (int np = 0; np < 4; np++) {
                unsigned vh[4];
                int vo = voff4 + kk * 2048 + np * 32;
                ldsm4t(vh, kvb + 16384 + SWZ(vo));
                MMA_F16(o[2 * np],     pa, vh[0], vh[1]);
                MMA_F16(o[2 * np + 1], pa, vh[2], vh[3]);
            }
        }
        l0r = l0r * a0 + lacc[0];
        l1r = l1r * a1 + lacc[2];
    }

    // epilogue
    float inv0 = 1.f / l0r, inv1 = 1.f / l1r;
    float* Og = g_O + ((size_t)(b * N_TOK + q0 + wrow + gid)) * DKV + h * 64;
    #pragma unroll
    for (int ni = 0; ni < 8; ni++) {
        int c = ni * 8 + 2 * tig;
        *(float2*)(Og + c)           = make_float2(o[ni][0] * inv0, o[ni][1] * inv0);
        *(float2*)(Og + 8 * DKV + c) = make_float2(o[ni][2] * inv1, o[ni][3] * inv1);
    }
}

// ---------------- launch ----------------
extern "C" void kernel_launch(void* const* d_in, const int* in_sizes, int n_in,
                              void* d_out, int out_size) {
    const float* hs = (const float*)d_in[0];
    const float* Wq = (const float*)d_in[1];
    const float* Wk = (const float*)d_in[2];
    const float* Wv = (const float*)d_in[3];
    const float* Wo = (const float*)d_in[4];
    const float* rb = (const float*)d_in[5];
    float* out = (float*)d_out;

    void *pWf, *pWoS, *pO;
    cudaGetSymbolAddress(&pWf, g_Wf);
    cudaGetSymbolAddress(&pWoS, g_WoS);
    cudaGetSymbolAddress(&pO, g_O);

    fold_kernel<<<1024, 256>>>(Wq, Wk, Wv, Wo, rb);

    cudaFuncSetAttribute(gemm_bf16, cudaFuncAttributeMaxDynamicSharedMemorySize, GSM_TOT);
    gemm_bf16<<<dim3(768 / GBN, M_TOTAL / GBM), 256, GSM_TOT>>>(
        hs, (const float*)pWf, nullptr, M_TOTAL, 768, DM, 1);

    cudaFuncSetAttribute(attn_mma, cudaFuncAttributeMaxDynamicSharedMemorySize, SM_TOT);
    attn_mma<<<dim3(N_TOK / QT, BATCH * 4), 256, SM_TOT>>>();

    gemm_bf16<<<dim3(DM / GBN, M_TOTAL / GBM), 256, GSM_TOT>>>(
        (const float*)pO, (const float*)pWoS, out, M_TOTAL, DM, DKV, 0);
}

// round 14
// speedup vs baseline: 1.7279x; 1.0681x over previous
#include <cuda_runtime.h>
#include <cuda_bf16.h>
#include <cuda_fp16.h>
#include <cstdint>
#include <cstddef>

#define N_TOK 2048
#define BATCH 4
#define DM    1024
#define DKV   256
#define M_TOTAL (BATCH * N_TOK)   // 8192
#define LOG2E 1.4426950408889634f
#define ONES16 0x3C003C00u

// ---- pipelined GEMM tiles (bf16 planes, 128B rows, SW128) ----
#define GBM 128
#define GBN 64
#define GBK 64
#define GA_H 0
#define GA_L 16384
#define GB_H 32768
#define GB_L 40960
#define GBUF 49152                 // one buffer
#define GSM_TOT (2 * GBUF)         // 98304 -> 2 CTAs/SM

// ---- attention smem map ----
#define QT 128
#define KT 64
#define KVSZ 24576                 // KH 8K | KL 8K | VH 8K
#define SM_QH 0
#define SM_QL 16384
#define SM_KV0 32768
#define SM_BI  (SM_KV0 + 2 * KVSZ) // 81920
#define SM_TOT (SM_BI + 2176 * 4)  // 90624 -> 2 CTAs/SM

// ---------------- scratch (bf16/fp16 planes everywhere) ----------------
__device__ float g_bias[4095 * 4];
__device__ __nv_bfloat16 g_hsH[M_TOTAL * DM];
__device__ __nv_bfloat16 g_hsL[M_TOTAL * DM];
__device__ __nv_bfloat16 g_WfH[768 * 1024];
__device__ __nv_bfloat16 g_WfL[768 * 1024];
__device__ __nv_bfloat16 g_WoH[1024 * 256];
__device__ __nv_bfloat16 g_WoL[1024 * 256];
__device__ __nv_bfloat16 g_QH[M_TOTAL * DKV];
__device__ __nv_bfloat16 g_QL[M_TOTAL * DKV];
__device__ __nv_bfloat16 g_KH[M_TOTAL * DKV];
__device__ __nv_bfloat16 g_KL[M_TOTAL * DKV];
__device__ __half        g_VH[M_TOTAL * DKV];
__device__ __nv_bfloat16 g_OH[M_TOTAL * DKV];
__device__ __nv_bfloat16 g_OL[M_TOTAL * DKV];

// ---------------- helpers ----------------
#define MMA_BF16(d, a, b0, b1)                                              \
    asm volatile("mma.sync.aligned.m16n8k16.row.col.f32.bf16.bf16.f32 "     \
        "{%0,%1,%2,%3}, {%4,%5,%6,%7}, {%8,%9}, {%0,%1,%2,%3};"             \
        : "+f"(d[0]), "+f"(d[1]), "+f"(d[2]), "+f"(d[3])                    \
        : "r"(a[0]), "r"(a[1]), "r"(a[2]), "r"(a[3]), "r"(b0), "r"(b1))

#define MMA_F16(d, a, b0, b1)                                               \
    asm volatile("mma.sync.aligned.m16n8k16.row.col.f32.f16.f16.f32 "       \
        "{%0,%1,%2,%3}, {%4,%5,%6,%7}, {%8,%9}, {%0,%1,%2,%3};"             \
        : "+f"(d[0]), "+f"(d[1]), "+f"(d[2]), "+f"(d[3])                    \
        : "r"(a[0]), "r"(a[1]), "r"(a[2]), "r"(a[3]), "r"(b0), "r"(b1))

__device__ __forceinline__ void ldsm4(unsigned* r, uint32_t addr) {
    asm volatile("ldmatrix.sync.aligned.m8n8.x4.shared.b16 {%0,%1,%2,%3}, [%4];"
                 : "=r"(r[0]), "=r"(r[1]), "=r"(r[2]), "=r"(r[3]) : "r"(addr));
}
__device__ __forceinline__ void ldsm4t(unsigned* r, uint32_t addr) {
    asm volatile("ldmatrix.sync.aligned.m8n8.x4.trans.shared.b16 {%0,%1,%2,%3}, [%4];"
                 : "=r"(r[0]), "=r"(r[1]), "=r"(r[2]), "=r"(r[3]) : "r"(addr));
}

__device__ __forceinline__ unsigned pk2(float e0, float e1) {
    unsigned r; asm("cvt.rn.bf16x2.f32 %0, %1, %2;" : "=r"(r) : "f"(e1), "f"(e0)); return r;
}
__device__ __forceinline__ unsigned pkh(float e0, float e1) {
    unsigned r; asm("cvt.rn.f16x2.f32 %0, %1, %2;" : "=r"(r) : "f"(e1), "f"(e0)); return r;
}

__device__ __forceinline__ uint32_t s2u(const void* p) {
    uint32_t a;
    asm("{ .reg .u64 t; cvta.to.shared.u64 t, %1; cvt.u32.u64 %0, t; }" : "=r"(a) : "l"(p));
    return a;
}

__device__ __forceinline__ void cpa16(uint32_t dst, const void* src) {
    asm volatile("cp.async.cg.shared.global [%0], [%1], 16;" :: "r"(dst), "l"(src));
}
#define CP_COMMIT() asm volatile("cp.async.commit_group;" ::: "memory")
#define CP_WAIT0()  asm volatile("cp.async.wait_group 0;" ::: "memory")

// FMA-pipe exp2, degree-5
__device__ __forceinline__ float exp2p(float t) {
    t = fmaxf(t, -126.f);
    float r = rintf(t);
    float f = t - r;
    int   i = (int)r;
    float p = 1.3333558e-3f;
    p = fmaf(p, f, 9.6181291e-3f);
    p = fmaf(p, f, 5.5504109e-2f);
    p = fmaf(p, f, 2.4022651e-1f);
    p = fmaf(p, f, 6.9314718e-1f);
    p = fmaf(p, f, 1.0f);
    return p * __int_as_float((i + 127) << 23);
}

#define SWZ(x) ((x) ^ (((x) >> 3) & 0x70))

// bf16 hi/lo pair to global planes (f32 inputs)
__device__ __forceinline__ void st_pair(__nv_bfloat16* H, __nv_bfloat16* L,
                                        size_t off, float a, float b) {
    unsigned hp = pk2(a, b);
    unsigned lp = pk2(a - __uint_as_float(hp << 16),
                      b - __uint_as_float(hp & 0xffff0000u));
    *(unsigned*)(H + off) = hp;
    *(unsigned*)(L + off) = lp;
}

// scalar hi/lo split
__device__ __forceinline__ void split1(float v, __nv_bfloat16* H, __nv_bfloat16* L, size_t off) {
    __nv_bfloat16 hb = __float2bfloat16(v);
    H[off] = hb;
    L[off] = __float2bfloat16(v - __bfloat162float(hb));
}

// ---------------- fold weights + bias ----------------
__global__ void fold_kernel(const float* __restrict__ Wq, const float* __restrict__ Wk,
                            const float* __restrict__ Wv, const float* __restrict__ Wo,
                            const float* __restrict__ rb) {
    int idx = blockIdx.x * blockDim.x + threadIdx.x;
    if (idx < 256 * 1024) {
        int r   = idx >> 10;
        int col = idx & 1023;
        int h = r >> 6, d = r & 63;
        float sq = 0.f, sk = 0.f, sv = 0.f;
        #pragma unroll
        for (int g = 0; g < 4; g++) {
            int src = ((g * 4 + h) * 64 + d) * 1024 + col;
            sq += Wq[src]; sk += Wk[src]; sv += Wv[src];
        }
        split1(sq * LOG2E, g_WfH, g_WfL, (size_t)r * 1024 + col);
        split1(sk * 0.25f, g_WfH, g_WfL, (size_t)(256 + r) * 1024 + col);
        split1(sv * 0.25f, g_WfH, g_WfL, (size_t)(512 + r) * 1024 + col);

        int j = idx >> 8;
        int c = idx & 255;
        float so = 0.f;
        #pragma unroll
        for (int g = 0; g < 4; g++) so += Wo[j * 1024 + g * 256 + c];
        split1(so, g_WoH, g_WoL, (size_t)j * 256 + c);
    }
    if (idx < 4095 * 4) {
        int i = idx >> 2, h = idx & 3;
        int rel = i - 2047;
        int bucket = (rel > 0) ? 16 : 0;
        int rp = rel < 0 ? -rel : rel;
        int lb;
        if (rp < 8) lb = rp;
        else {
            int cnt = (rp >= 12) + (rp >= 16) + (rp >= 23) + (rp >= 32) +
                      (rp >= 46) + (rp >= 64) + (rp >= 91);
            lb = 8 + cnt;
        }
        bucket += lb;
        float s = 0.f;
        #pragma unroll
        for (int g = 0; g < 4; g++) s += rb[bucket * 16 + g * 4 + h];
        g_bias[idx] = s * 0.25f * LOG2E;
    }
}

// ---------------- split hidden states once (float4 -> hi/lo planes) ----------------
__global__ void hsplit_kernel(const float* __restrict__ hs) {
    int idx = blockIdx.x * blockDim.x + threadIdx.x;   // float4 index, 2097152 total
    float4 v = ((const float4*)hs)[idx];
    unsigned h01 = pk2(v.x, v.y), h23 = pk2(v.z, v.w);
    unsigned l01 = pk2(v.x - __uint_as_float(h01 << 16),
                       v.y - __uint_as_float(h01 & 0xffff0000u));
    unsigned l23 = pk2(v.z - __uint_as_float(h23 << 16),
                       v.w - __uint_as_float(h23 & 0xffff0000u));
    ((uint2*)g_hsH)[idx] = make_uint2(h01, h23);
    ((uint2*)g_hsL)[idx] = make_uint2(l01, l23);
}

// ---------------- pipelined plane GEMM: C[M,N] = A[M,K] * B[N,K]^T ----------------
// A/B pre-split bf16 hi/lo planes. cp.async double-buffered. 3-term hi/lo MMA.
// mode 0: C f32. mode 1: QKV epilogue.
__device__ __forceinline__ void gprefetch(
    uint32_t buf, const __nv_bfloat16* AH, const __nv_bfloat16* AL,
    const __nv_bfloat16* BH, const __nv_bfloat16* BL,
    int m0, int n0, int kt, int K, int tid) {
    #pragma unroll
    for (int p = 0; p < 4; p++) {            // A: 128 rows x 8 chunks
        int f = tid + p * 256;
        int row = f >> 3, c8 = f & 7;
        size_t go = (size_t)(m0 + row) * K + kt + c8 * 8;
        int so = SWZ(row * 128 + c8 * 16);
        cpa16(buf + GA_H + so, AH + go);
        cpa16(buf + GA_L + so, AL + go);
    }
    #pragma unroll
    for (int p = 0; p < 2; p++) {            // B: 64 rows x 8 chunks
        int f = tid + p * 256;
        int row = f >> 3, c8 = f & 7;
        size_t go = (size_t)(n0 + row) * K + kt + c8 * 8;
        int so = SWZ(row * 128 + c8 * 16);
        cpa16(buf + GB_H + so, BH + go);
        cpa16(buf + GB_L + so, BL + go);
    }
}

__global__ __launch_bounds__(256, 2)
void gemm_bf16p(const __nv_bfloat16* __restrict__ AH, const __nv_bfloat16* __restrict__ AL,
                const __nv_bfloat16* __restrict__ BH, const __nv_bfloat16* __restrict__ BL,
                float* __restrict__ C, int M, int N, int K, int mode) {
    extern __shared__ char smem[];
    uint32_t sb = s2u(smem);

    int tid  = threadIdx.x;
    int lane = tid & 31, warp = tid >> 5;
    int wm = warp >> 1, wn = warp & 1;
    int gid = lane >> 2, tig = lane & 3;
    int q8 = lane >> 3, r8 = lane & 7;
    int m0 = blockIdx.y * GBM, n0 = blockIdx.x * GBN;

    float acc[2][4][4];
    #pragma unroll
    for (int mi = 0; mi < 2; mi++)
        #pragma unroll
        for (int ni = 0; ni < 4; ni++)
            #pragma unroll
            for (int r = 0; r < 4; r++) acc[mi][ni][r] = 0.f;

    gprefetch(sb, AH, AL, BH, BL, m0, n0, 0, K, tid);
    CP_COMMIT();

    int iters = K / GBK;
    for (int t = 0; t < iters; t++) {
        CP_WAIT0();
        __syncthreads();
        if (t + 1 < iters) {
            gprefetch(sb + ((t + 1) & 1) * GBUF, AH, AL, BH, BL,
                      m0, n0, (t + 1) * GBK, K, tid);
            CP_COMMIT();
        }
        uint32_t bb = sb + (t & 1) * GBUF;

        #pragma unroll
        for (int kb = 0; kb < 4; kb++) {
            unsigned ah[2][4], al[2][4];
            #pragma unroll
            for (int mi = 0; mi < 2; mi++) {
                int ao = (wm * 32 + mi * 16 + ((q8 & 1) ? 8 : 0) + r8) * 128
                       + ((q8 & 2) ? 16 : 0) + kb * 32;
                ldsm4(ah[mi], bb + GA_H + SWZ(ao));
                ldsm4(al[mi], bb + GA_L + SWZ(ao));
            }
            #pragma unroll
            for (int ng = 0; ng < 2; ng++) {
                unsigned bh[4], bl[4];
                int bo = (wn * 32 + ng * 16 + ((q8 & 2) ? 8 : 0) + r8) * 128
                       + ((q8 & 1) ? 16 : 0) + kb * 32;
                ldsm4(bh, bb + GB_H + SWZ(bo));
                ldsm4(bl, bb + GB_L + SWZ(bo));
                #pragma unroll
                for (int mi = 0; mi < 2; mi++) {
                    MMA_BF16(acc[mi][2 * ng],     ah[mi], bh[0], bh[1]);
                    MMA_BF16(acc[mi][2 * ng],     al[mi], bh[0], bh[1]);
                    MMA_BF16(acc[mi][2 * ng],     ah[mi], bl[0], bl[1]);
                    MMA_BF16(acc[mi][2 * ng + 1], ah[mi], bh[2], bh[3]);
                    MMA_BF16(acc[mi][2 * ng + 1], al[mi], bh[2], bh[3]);
                    MMA_BF16(acc[mi][2 * ng + 1], ah[mi], bl[2], bl[3]);
                }
            }
        }
    }

    #pragma unroll
    for (int mi = 0; mi < 2; mi++) {
        #pragma unroll
        for (int ni = 0; ni < 4; ni++) {
            int row0 = m0 + wm * 32 + mi * 16 + gid;
            int ncol = n0 + wn * 32 + ni * 8 + tig * 2;
            float* a4 = acc[mi][ni];
            if (mode == 0) {
                *(float2*)(C + (size_t)row0 * N + ncol)       = make_float2(a4[0], a4[1]);
                *(float2*)(C + (size_t)(row0 + 8) * N + ncol) = make_float2(a4[2], a4[3]);
            } else {
                int buf = ncol >> 8, rem = ncol & 255;
                size_t o0 = (size_t)row0 * DKV + rem;
                size_t o1 = (size_t)(row0 + 8) * DKV + rem;
                if (buf == 0) {
                    st_pair(g_QH, g_QL, o0, a4[0], a4[1]);
                    st_pair(g_QH, g_QL, o1, a4[2], a4[3]);
                } else if (buf == 1) {
                    st_pair(g_KH, g_KL, o0, a4[0], a4[1]);
                    st_pair(g_KH, g_KL, o1, a4[2], a4[3]);
                } else {
                    *(unsigned*)(g_VH + o0) = pkh(a4[0], a4[1]);
                    *(unsigned*)(g_VH + o1) = pkh(a4[2], a4[3]);
                }
            }
        }
    }
}

// ---------------- KV prefetch ----------------
__device__ __forceinline__ void prefetch_kv(
    uint32_t kvb, const __nv_bfloat16* KH, const __nv_bfloat16* KL,
    const __half* VH, int kv0, int tid) {
    #pragma unroll
    for (int p = 0; p < 2; p++) {
        int f = tid + p * 256;
        int row = f >> 3, c8 = f & 7;
        size_t go = (size_t)(kv0 + row) * DKV + c8 * 8;
        int so = SWZ(row * 128 + c8 * 16);
        cpa16(kvb + so,         KH + go);
        cpa16(kvb + 8192 + so,  KL + go);
        cpa16(kvb + 16384 + so, VH + go);
    }
}

// ---------------- flash attention (unchanged core; O -> bf16 planes) ----------------
__global__ __launch_bounds__(256, 2)
void attn_mma() {
    extern __shared__ char smem[];
    uint32_t sb = s2u(smem);
    int tid = threadIdx.x;
    int lane = tid & 31, w = tid >> 5;
    int gid = lane >> 2, tig = lane & 3;
    int wrow = w * 16;
    int q0 = blockIdx.x * QT;
    int bh = blockIdx.y;
    int b = bh >> 2, h = bh & 3;

    float* biass = (float*)(smem + SM_BI);
    for (int i = tid; i < 2176; i += 256) {
        int t = i - 127 - q0 + 2047;
        t = max(0, min(4094, t));
        biass[i] = g_bias[t * 4 + h];
    }

    size_t base = (size_t)(b * N_TOK) * DKV + h * 64;
    const __nv_bfloat16* QHg = g_QH + base + (size_t)q0 * DKV;
    const __nv_bfloat16* QLg = g_QL + base + (size_t)q0 * DKV;
    const __nv_bfloat16* KHg = g_KH + base;
    const __nv_bfloat16* KLg = g_KL + base;
    const __half* VHg = g_VH + base;

    #pragma unroll
    for (int p = 0; p < 4; p++) {
        int f = tid + p * 256;
        int row = f >> 3, c8 = f & 7;
        size_t go = (size_t)row * DKV + c8 * 8;
        int so = SWZ(row * 128 + c8 * 16);
        cpa16(sb + SM_QH + so, QHg + go);
        cpa16(sb + SM_QL + so, QLg + go);
    }
    prefetch_kv(sb + SM_KV0, KHg, KLg, VHg, 0, tid);
    CP_COMMIT();

    int mi = lane >> 3, r8 = lane & 7;
    int aoff = (wrow + ((mi & 1) ? 8 : 0) + r8) * 128 + ((mi & 2) ? 16 : 0);
    int boff = (((mi & 2) ? 8 : 0) + r8) * 128 + ((mi & 1) ? 16 : 0);
    int voff4 = (lane & 15) * 128 + (lane >> 4) * 16;

    float m0r = -1e30f, m1r = -1e30f, l0r = 0.f, l1r = 0.f;
    float o[8][4];
    #pragma unroll
    for (int ni = 0; ni < 8; ni++)
        #pragma unroll
        for (int q = 0; q < 4; q++) o[ni][q] = 0.f;

    for (int kv0 = 0, t = 0; kv0 < N_TOK; kv0 += KT, t++) {
        CP_WAIT0();
        __syncthreads();
        if (kv0 + KT < N_TOK) {
            prefetch_kv(sb + SM_KV0 + ((t + 1) & 1) * KVSZ,
                        KHg, KLg, VHg, kv0 + KT, tid);
            CP_COMMIT();
        }
        uint32_t kvb = sb + SM_KV0 + (t & 1) * KVSZ;

        float s[8][4];
        #pragma unroll
        for (int ni = 0; ni < 8; ni++)
            #pragma unroll
            for (int q = 0; q < 4; q++) s[ni][q] = 0.f;

        #pragma unroll
        for (int ks = 0; ks < 4; ks++) {
            unsigned qh[4], ql[4];
            ldsm4(qh, sb + SM_QH + SWZ(aoff + ks * 32));
            ldsm4(ql, sb + SM_QL + SWZ(aoff + ks * 32));
            #pragma unroll
            for (int np = 0; np < 4; np++) {
                unsigned kh[4], kl[4];
                int bo = boff + np * 2048 + ks * 32;
                ldsm4(kh, kvb + SWZ(bo));
                ldsm4(kl, kvb + 8192 + SWZ(bo));
                MMA_BF16(s[2 * np],     qh, kh[0], kh[1]);
                MMA_BF16(s[2 * np],     ql, kh[0], kh[1]);
                MMA_BF16(s[2 * np],     qh, kl[0], kl[1]);
                MMA_BF16(s[2 * np + 1], qh, kh[2], kh[3]);
                MMA_BF16(s[2 * np + 1], ql, kh[2], kh[3]);
                MMA_BF16(s[2 * np + 1], qh, kl[2], kl[3]);
            }
        }

        const float* bp0 = biass + (kv0 + 127 - wrow - gid);
        #pragma unroll
        for (int ni = 0; ni < 8; ni++) {
            int c = ni * 8 + 2 * tig;
            s[ni][0] += bp0[c];
            s[ni][1] += bp0[c + 1];
            s[ni][2] += bp0[c - 8];
            s[ni][3] += bp0[c - 7];
        }

        float mx0 = -1e30f, mx1 = -1e30f;
        #pragma unroll
        for (int ni = 0; ni < 8; ni++) {
            mx0 = fmaxf(mx0, fmaxf(s[ni][0], s[ni][1]));
            mx1 = fmaxf(mx1, fmaxf(s[ni][2], s[ni][3]));
        }
        mx0 = fmaxf(mx0, __shfl_xor_sync(0xffffffffu, mx0, 1));
        mx0 = fmaxf(mx0, __shfl_xor_sync(0xffffffffu, mx0, 2));
        mx1 = fmaxf(mx1, __shfl_xor_sync(0xffffffffu, mx1, 1));
        mx1 = fmaxf(mx1, __shfl_xor_sync(0xffffffffu, mx1, 2));
        float mn0 = fmaxf(m0r, mx0), mn1 = fmaxf(m1r, mx1);
        float a0 = exp2p(m0r - mn0), a1 = exp2p(m1r - mn1);
        m0r = mn0; m1r = mn1;

        #pragma unroll
        for (int ni = 0; ni < 8; ni++) {
            s[ni][0] = exp2p(s[ni][0] - mn0);
            s[ni][1] = exp2p(s[ni][1] - mn0);
            s[ni][2] = exp2p(s[ni][2] - mn1);
            s[ni][3] = exp2p(s[ni][3] - mn1);
        }

        #pragma unroll
        for (int ni = 0; ni < 8; ni++) {
            o[ni][0] *= a0; o[ni][1] *= a0;
            o[ni][2] *= a1; o[ni][3] *= a1;
        }

        float lacc[4] = {0.f, 0.f, 0.f, 0.f};
        #pragma unroll
        for (int kk = 0; kk < 4; kk++) {
            unsigned pa[4];
            pa[0] = pkh(s[2 * kk][0],     s[2 * kk][1]);
            pa[1] = pkh(s[2 * kk][2],     s[2 * kk][3]);
            pa[2] = pkh(s[2 * kk + 1][0], s[2 * kk + 1][1]);
            pa[3] = pkh(s[2 * kk + 1][2], s[2 * kk + 1][3]);
            MMA_F16(lacc, pa, ONES16, ONES16);
            #pragma unroll
            for (int np = 0; np < 4; np++) {
                unsigned vh[4];
                int vo = voff4 + kk * 2048 + np * 32;
                ldsm4t(vh, kvb + 16384 + SWZ(vo));
                MMA_F16(o[2 * np],     pa, vh[0], vh[1]);
                MMA_F16(o[2 * np + 1], pa, vh[2], vh[3]);
            }
        }
        l0r = l0r * a0 + lacc[0];
        l1r = l1r * a1 + lacc[2];
    }

    // epilogue: O -> bf16 hi/lo planes
    float inv0 = 1.f / l0r, inv1 = 1.f / l1r;
    size_t orow0 = (size_t)(b * N_TOK + q0 + wrow + gid) * DKV + h * 64;
    #pragma unroll
    for (int ni = 0; ni < 8; ni++) {
        int c = ni * 8 + 2 * tig;
        st_pair(g_OH, g_OL, orow0 + c,           o[ni][0] * inv0, o[ni][1] * inv0);
        st_pair(g_OH, g_OL, orow0 + 8 * DKV + c, o[ni][2] * inv1, o[ni][3] * inv1);
    }
}

// ---------------- launch ----------------
extern "C" void kernel_launch(void* const* d_in, const int* in_sizes, int n_in,
                              void* d_out, int out_size) {
    const float* hs = (const float*)d_in[0];
    const float* Wq = (const float*)d_in[1];
    const float* Wk = (const float*)d_in[2];
    const float* Wv = (const float*)d_in[3];
    const float* Wo = (const float*)d_in[4];
    const float* rb = (const float*)d_in[5];
    float* out = (float*)d_out;

    void *phsH, *phsL, *pWfH, *pWfL, *pWoH, *pWoL, *pOH, *pOL;
    cudaGetSymbolAddress(&phsH, g_hsH);
    cudaGetSymbolAddress(&phsL, g_hsL);
    cudaGetSymbolAddress(&pWfH, g_WfH);
    cudaGetSymbolAddress(&pWfL, g_WfL);
    cudaGetSymbolAddress(&pWoH, g_WoH);
    cudaGetSymbolAddress(&pWoL, g_WoL);
    cudaGetSymbolAddress(&pOH, g_OH);
    cudaGetSymbolAddress(&pOL, g_OL);

    fold_kernel<<<1024, 256>>>(Wq, Wk, Wv, Wo, rb);                       // 0
    hsplit_kernel<<<8192, 256>>>(hs);                                     // 1

    cudaFuncSetAttribute(gemm_bf16p, cudaFuncAttributeMaxDynamicSharedMemorySize, GSM_TOT);
    gemm_bf16p<<<dim3(768 / GBN, M_TOTAL / GBM), 256, GSM_TOT>>>(         // 2: proj
        (const __nv_bfloat16*)phsH, (const __nv_bfloat16*)phsL,
        (const __nv_bfloat16*)pWfH, (const __nv_bfloat16*)pWfL,
        nullptr, M_TOTAL, 768, DM, 1);

    cudaFuncSetAttribute(attn_mma, cudaFuncAttributeMaxDynamicSharedMemorySize, SM_TOT);
    attn_mma<<<dim3(N_TOK / QT, BATCH * 4), 256, SM_TOT>>>();             // 3

    gemm_bf16p<<<dim3(DM / GBN, M_TOTAL / GBM), 256, GSM_TOT>>>(          // 4: out
        (const __nv_bfloat16*)pOH, (const __nv_bfloat16*)pOL,
        (const __nv_bfloat16*)pWoH, (const __nv_bfloat16*)pWoL,
        out, M_TOTAL, DM, DKV, 0);
}

// round 16
// speedup vs baseline: 1.7694x; 1.0240x over previous
#include <cuda_runtime.h>
#include <cuda_bf16.h>
#include <cuda_fp16.h>
#include <cstdint>
#include <cstddef>

#define N_TOK 2048
#define BATCH 4
#define DM    1024
#define DKV   256
#define M_TOTAL (BATCH * N_TOK)   // 8192
#define LOG2E 1.4426950408889634f
#define ONES16 0x3C003C00u
#define MAGIC 12582912.f           // 1.5 * 2^23

// ---- pipelined GEMM tiles (bf16 planes, 128B rows, SW128) ----
#define GBM 128
#define GBN 64
#define GBK 64
#define GA_H 0
#define GA_L 16384
#define GB_H 32768
#define GB_L 40960
#define GBUF 49152
#define GSM_TOT (2 * GBUF)

// ---- attention smem map ----
#define QT 128
#define KT 64
#define KVSZ 24576                 // KH 8K | KL 8K | VH 8K
#define SM_QH 0
#define SM_QL 16384
#define SM_KV0 32768
#define SM_BI  (SM_KV0 + 2 * KVSZ) // 81920
#define SM_TOT (SM_BI + 2176 * 4)  // 90624 -> 2 CTAs/SM

// ---------------- scratch ----------------
__device__ float g_bias[4095 * 4];
__device__ __nv_bfloat16 g_hsH[M_TOTAL * DM];
__device__ __nv_bfloat16 g_hsL[M_TOTAL * DM];
__device__ __nv_bfloat16 g_WfH[768 * 1024];
__device__ __nv_bfloat16 g_WfL[768 * 1024];
__device__ __nv_bfloat16 g_WoH[1024 * 256];
__device__ __nv_bfloat16 g_WoL[1024 * 256];
__device__ __nv_bfloat16 g_QH[M_TOTAL * DKV];
__device__ __nv_bfloat16 g_QL[M_TOTAL * DKV];
__device__ __nv_bfloat16 g_KH[M_TOTAL * DKV];
__device__ __nv_bfloat16 g_KL[M_TOTAL * DKV];
__device__ __half        g_VH[M_TOTAL * DKV];
__device__ __nv_bfloat16 g_OH[M_TOTAL * DKV];
__device__ __nv_bfloat16 g_OL[M_TOTAL * DKV];

// ---------------- helpers ----------------
#define MMA_BF16(d, a, b0, b1)                                              \
    asm volatile("mma.sync.aligned.m16n8k16.row.col.f32.bf16.bf16.f32 "     \
        "{%0,%1,%2,%3}, {%4,%5,%6,%7}, {%8,%9}, {%0,%1,%2,%3};"             \
        : "+f"(d[0]), "+f"(d[1]), "+f"(d[2]), "+f"(d[3])                    \
        : "r"(a[0]), "r"(a[1]), "r"(a[2]), "r"(a[3]), "r"(b0), "r"(b1))

#define MMA_F16(d, a, b0, b1)                                               \
    asm volatile("mma.sync.aligned.m16n8k16.row.col.f32.f16.f16.f32 "       \
        "{%0,%1,%2,%3}, {%4,%5,%6,%7}, {%8,%9}, {%0,%1,%2,%3};"             \
        : "+f"(d[0]), "+f"(d[1]), "+f"(d[2]), "+f"(d[3])                    \
        : "r"(a[0]), "r"(a[1]), "r"(a[2]), "r"(a[3]), "r"(b0), "r"(b1))

__device__ __forceinline__ void ldsm4(unsigned* r, uint32_t addr) {
    asm volatile("ldmatrix.sync.aligned.m8n8.x4.shared.b16 {%0,%1,%2,%3}, [%4];"
                 : "=r"(r[0]), "=r"(r[1]), "=r"(r[2]), "=r"(r[3]) : "r"(addr));
}
__device__ __forceinline__ void ldsm4t(unsigned* r, uint32_t addr) {
    asm volatile("ldmatrix.sync.aligned.m8n8.x4.trans.shared.b16 {%0,%1,%2,%3}, [%4];"
                 : "=r"(r[0]), "=r"(r[1]), "=r"(r[2]), "=r"(r[3]) : "r"(addr));
}

__device__ __forceinline__ unsigned pk2(float e0, float e1) {
    unsigned r; asm("cvt.rn.bf16x2.f32 %0, %1, %2;" : "=r"(r) : "f"(e1), "f"(e0)); return r;
}
__device__ __forceinline__ unsigned pkh(float e0, float e1) {
    unsigned r; asm("cvt.rn.f16x2.f32 %0, %1, %2;" : "=r"(r) : "f"(e1), "f"(e0)); return r;
}

__device__ __forceinline__ uint32_t s2u(const void* p) {
    uint32_t a;
    asm("{ .reg .u64 t; cvta.to.shared.u64 t, %1; cvt.u32.u64 %0, t; }" : "=r"(a) : "l"(p));
    return a;
}

__device__ __forceinline__ void cpa16(uint32_t dst, const void* src) {
    asm volatile("cp.async.cg.shared.global [%0], [%1], 16;" :: "r"(dst), "l"(src));
}
#define CP_COMMIT() asm volatile("cp.async.commit_group;" ::: "memory")
#define CP_WAIT0()  asm volatile("cp.async.wait_group 0;" ::: "memory")

// magic-number exp2: returns 2^(s - mn') where Cm = MAGIC - mn rounds mn to the
// integer mn' (ulp=1 at 2^23). All users of one Cm are mutually consistent; the
// flash m-register must store mn' (= MAGIC - Cm, Sterbenz-exact), making the
// alpha rescale chain bit-exact (integer exponent deltas, f == 0).
__device__ __forceinline__ float exp2m(float s, float Cm) {
    float z = fmaxf(s + Cm, MAGIC - 126.f);
    float u = z - Cm;
    float f = fmaxf(s - u, -0.5f);
    float p = 9.6181291e-3f;
    p = fmaf(p, f, 5.5504109e-2f);
    p = fmaf(p, f, 2.4022651e-1f);
    p = fmaf(p, f, 6.9314718e-1f);
    p = fmaf(p, f, 1.0f);
    return __int_as_float(__float_as_int(p) + (__float_as_int(z) << 23));
}

#define SWZ(x) ((x) ^ (((x) >> 3) & 0x70))

__device__ __forceinline__ void st_pair(__nv_bfloat16* H, __nv_bfloat16* L,
                                        size_t off, float a, float b) {
    unsigned hp = pk2(a, b);
    unsigned lp = pk2(a - __uint_as_float(hp << 16),
                      b - __uint_as_float(hp & 0xffff0000u));
    *(unsigned*)(H + off) = hp;
    *(unsigned*)(L + off) = lp;
}

__device__ __forceinline__ void split1(float v, __nv_bfloat16* H, __nv_bfloat16* L, size_t off) {
    __nv_bfloat16 hb = __float2bfloat16(v);
    H[off] = hb;
    L[off] = __float2bfloat16(v - __bfloat162float(hb));
}

// ---------------- fold weights + bias ----------------
__global__ void fold_kernel(const float* __restrict__ Wq, const float* __restrict__ Wk,
                            const float* __restrict__ Wv, const float* __restrict__ Wo,
                            const float* __restrict__ rb) {
    int idx = blockIdx.x * blockDim.x + threadIdx.x;
    if (idx < 256 * 1024) {
        int r   = idx >> 10;
        int col = idx & 1023;
        int h = r >> 6, d = r & 63;
        float sq = 0.f, sk = 0.f, sv = 0.f;
        #pragma unroll
        for (int g = 0; g < 4; g++) {
            int src = ((g * 4 + h) * 64 + d) * 1024 + col;
            sq += Wq[src]; sk += Wk[src]; sv += Wv[src];
        }
        split1(sq * LOG2E, g_WfH, g_WfL, (size_t)r * 1024 + col);
        split1(sk * 0.25f, g_WfH, g_WfL, (size_t)(256 + r) * 1024 + col);
        split1(sv * 0.25f, g_WfH, g_WfL, (size_t)(512 + r) * 1024 + col);

        int j = idx >> 8;
        int c = idx & 255;
        float so = 0.f;
        #pragma unroll
        for (int g = 0; g < 4; g++) so += Wo[j * 1024 + g * 256 + c];
        split1(so, g_WoH, g_WoL, (size_t)j * 256 + c);
    }
    if (idx < 4095 * 4) {
        int i = idx >> 2, h = idx & 3;
        int rel = i - 2047;
        int bucket = (rel > 0) ? 16 : 0;
        int rp = rel < 0 ? -rel : rel;
        int lb;
        if (rp < 8) lb = rp;
        else {
            int cnt = (rp >= 12) + (rp >= 16) + (rp >= 23) + (rp >= 32) +
                      (rp >= 46) + (rp >= 64) + (rp >= 91);
            lb = 8 + cnt;
        }
        bucket += lb;
        float s = 0.f;
        #pragma unroll
        for (int g = 0; g < 4; g++) s += rb[bucket * 16 + g * 4 + h];
        g_bias[idx] = s * 0.25f * LOG2E;
    }
}

// ---------------- split hidden states once ----------------
__global__ void hsplit_kernel(const float* __restrict__ hs) {
    int idx = blockIdx.x * blockDim.x + threadIdx.x;
    float4 v = ((const float4*)hs)[idx];
    unsigned h01 = pk2(v.x, v.y), h23 = pk2(v.z, v.w);
    unsigned l01 = pk2(v.x - __uint_as_float(h01 << 16),
                       v.y - __uint_as_float(h01 & 0xffff0000u));
    unsigned l23 = pk2(v.z - __uint_as_float(h23 << 16),
                       v.w - __uint_as_float(h23 & 0xffff0000u));
    ((uint2*)g_hsH)[idx] = make_uint2(h01, h23);
    ((uint2*)g_hsL)[idx] = make_uint2(l01, l23);
}

// ---------------- pipelined plane GEMM ----------------
__device__ __forceinline__ void gprefetch(
    uint32_t buf, const __nv_bfloat16* AH, const __nv_bfloat16* AL,
    const __nv_bfloat16* BH, const __nv_bfloat16* BL,
    int m0, int n0, int kt, int K, int tid) {
    #pragma unroll
    for (int p = 0; p < 4; p++) {
        int f = tid + p * 256;
        int row = f >> 3, c8 = f & 7;
        size_t go = (size_t)(m0 + row) * K + kt + c8 * 8;
        int so = SWZ(row * 128 + c8 * 16);
        cpa16(buf + GA_H + so, AH + go);
        cpa16(buf + GA_L + so, AL + go);
    }
    #pragma unroll
    for (int p = 0; p < 2; p++) {
        int f = tid + p * 256;
        int row = f >> 3, c8 = f & 7;
        size_t go = (size_t)(n0 + row) * K + kt + c8 * 8;
        int so = SWZ(row * 128 + c8 * 16);
        cpa16(buf + GB_H + so, BH + go);
        cpa16(buf + GB_L + so, BL + go);
    }
}

__global__ __launch_bounds__(256, 2)
void gemm_bf16p(const __nv_bfloat16* __restrict__ AH, const __nv_bfloat16* __restrict__ AL,
                const __nv_bfloat16* __restrict__ BH, const __nv_bfloat16* __restrict__ BL,
                float* __restrict__ C, int M, int N, int K, int mode) {
    extern __shared__ char smem[];
    uint32_t sb = s2u(smem);

    int tid  = threadIdx.x;
    int lane = tid & 31, warp = tid >> 5;
    int wm = warp >> 1, wn = warp & 1;
    int gid = lane >> 2, tig = lane & 3;
    int q8 = lane >> 3, r8 = lane & 7;
    int m0 = blockIdx.y * GBM, n0 = blockIdx.x * GBN;

    float acc[2][4][4];
    #pragma unroll
    for (int mi = 0; mi < 2; mi++)
        #pragma unroll
        for (int ni = 0; ni < 4; ni++)
            #pragma unroll
            for (int r = 0; r < 4; r++) acc[mi][ni][r] = 0.f;

    gprefetch(sb, AH, AL, BH, BL, m0, n0, 0, K, tid);
    CP_COMMIT();

    int iters = K / GBK;
    for (int t = 0; t < iters; t++) {
        CP_WAIT0();
        __syncthreads();
        if (t + 1 < iters) {
            gprefetch(sb + ((t + 1) & 1) * GBUF, AH, AL, BH, BL,
                      m0, n0, (t + 1) * GBK, K, tid);
            CP_COMMIT();
        }
        uint32_t bb = sb + (t & 1) * GBUF;

        #pragma unroll
        for (int kb = 0; kb < 4; kb++) {
            unsigned ah[2][4], al[2][4];
            #pragma unroll
            for (int mi = 0; mi < 2; mi++) {
                int ao = (wm * 32 + mi * 16 + ((q8 & 1) ? 8 : 0) + r8) * 128
                       + ((q8 & 2) ? 16 : 0) + kb * 32;
                ldsm4(ah[mi], bb + GA_H + SWZ(ao));
                ldsm4(al[mi], bb + GA_L + SWZ(ao));
            }
            #pragma unroll
            for (int ng = 0; ng < 2; ng++) {
                unsigned bh[4], bl[4];
                int bo = (wn * 32 + ng * 16 + ((q8 & 2) ? 8 : 0) + r8) * 128
                       + ((q8 & 1) ? 16 : 0) + kb * 32;
                ldsm4(bh, bb + GB_H + SWZ(bo));
                ldsm4(bl, bb + GB_L + SWZ(bo));
                #pragma unroll
                for (int mi = 0; mi < 2; mi++) {
                    MMA_BF16(acc[mi][2 * ng],     ah[mi], bh[0], bh[1]);
                    MMA_BF16(acc[mi][2 * ng + 1], ah[mi], bh[2], bh[3]);
                    MMA_BF16(acc[mi][2 * ng],     al[mi], bh[0], bh[1]);
                    MMA_BF16(acc[mi][2 * ng + 1], al[mi], bh[2], bh[3]);
                    MMA_BF16(acc[mi][2 * ng],     ah[mi], bl[0], bl[1]);
                    MMA_BF16(acc[mi][2 * ng + 1], ah[mi], bl[2], bl[3]);
                }
            }
        }
    }

    #pragma unroll
    for (int mi = 0; mi < 2; mi++) {
        #pragma unroll
        for (int ni = 0; ni < 4; ni++) {
            int row0 = m0 + wm * 32 + mi * 16 + gid;
            int ncol = n0 + wn * 32 + ni * 8 + tig * 2;
            float* a4 = acc[mi][ni];
            if (mode == 0) {
                *(float2*)(C + (size_t)row0 * N + ncol)       = make_float2(a4[0], a4[1]);
                *(float2*)(C + (size_t)(row0 + 8) * N + ncol) = make_float2(a4[2], a4[3]);
            } else {
                int buf = ncol >> 8, rem = ncol & 255;
                size_t o0 = (size_t)row0 * DKV + rem;
                size_t o1 = (size_t)(row0 + 8) * DKV + rem;
                if (buf == 0) {
                    st_pair(g_QH, g_QL, o0, a4[0], a4[1]);
                    st_pair(g_QH, g_QL, o1, a4[2], a4[3]);
                } else if (buf == 1) {
                    st_pair(g_KH, g_KL, o0, a4[0], a4[1]);
                    st_pair(g_KH, g_KL, o1, a4[2], a4[3]);
                } else {
                    *(unsigned*)(g_VH + o0) = pkh(a4[0], a4[1]);
                    *(unsigned*)(g_VH + o1) = pkh(a4[2], a4[3]);
                }
            }
        }
    }
}

// ---------------- KV prefetch ----------------
__device__ __forceinline__ void prefetch_kv(
    uint32_t kvb, const __nv_bfloat16* KH, const __nv_bfloat16* KL,
    const __half* VH, int kv0, int tid) {
    #pragma unroll
    for (int p = 0; p < 2; p++) {
        int f = tid + p * 256;
        int row = f >> 3, c8 = f & 7;
        size_t go = (size_t)(kv0 + row) * DKV + c8 * 8;
        int so = SWZ(row * 128 + c8 * 16);
        cpa16(kvb + so,         KH + go);
        cpa16(kvb + 8192 + so,  KL + go);
        cpa16(kvb + 16384 + so, VH + go);
    }
}

// ---------------- flash attention ----------------
__global__ __launch_bounds__(256, 2)
void attn_mma() {
    extern __shared__ char smem[];
    uint32_t sb = s2u(smem);
    int tid = threadIdx.x;
    int lane = tid & 31, w = tid >> 5;
    int gid = lane >> 2, tig = lane & 3;
    int wrow = w * 16;
    int q0 = blockIdx.x * QT;
    int bh = blockIdx.y;
    int b = bh >> 2, h = bh & 3;

    float* biass = (float*)(smem + SM_BI);
    for (int i = tid; i < 2176; i += 256) {
        int t = i - 127 - q0 + 2047;
        t = max(0, min(4094, t));
        biass[i] = g_bias[t * 4 + h];
    }

    size_t base = (size_t)(b * N_TOK) * DKV + h * 64;
    const __nv_bfloat16* QHg = g_QH + base + (size_t)q0 * DKV;
    const __nv_bfloat16* QLg = g_QL + base + (size_t)q0 * DKV;
    const __nv_bfloat16* KHg = g_KH + base;
    const __nv_bfloat16* KLg = g_KL + base;
    const __half* VHg = g_VH + base;

    #pragma unroll
    for (int p = 0; p < 4; p++) {
        int f = tid + p * 256;
        int row = f >> 3, c8 = f & 7;
        size_t go = (size_t)row * DKV + c8 * 8;
        int so = SWZ(row * 128 + c8 * 16);
        cpa16(sb + SM_QH + so, QHg + go);
        cpa16(sb + SM_QL + so, QLg + go);
    }
    prefetch_kv(sb + SM_KV0, KHg, KLg, VHg, 0, tid);
    CP_COMMIT();

    int mi = lane >> 3, r8 = lane & 7;
    int aoff = (wrow + ((mi & 1) ? 8 : 0) + r8) * 128 + ((mi & 2) ? 16 : 0);
    int boff = (((mi & 2) ? 8 : 0) + r8) * 128 + ((mi & 1) ? 16 : 0);
    int voff4 = (lane & 15) * 128 + (lane >> 4) * 16;

    float m0r = -1e30f, m1r = -1e30f, l0r = 0.f, l1r = 0.f;
    float o[8][4];
    #pragma unroll
    for (int ni = 0; ni < 8; ni++)
        #pragma unroll
        for (int q = 0; q < 4; q++) o[ni][q] = 0.f;

    for (int kv0 = 0, t = 0; kv0 < N_TOK; kv0 += KT, t++) {
        CP_WAIT0();
        __syncthreads();
        if (kv0 + KT < N_TOK) {
            prefetch_kv(sb + SM_KV0 + ((t + 1) & 1) * KVSZ,
                        KHg, KLg, VHg, kv0 + KT, tid);
            CP_COMMIT();
        }
        uint32_t kvb = sb + SM_KV0 + (t & 1) * KVSZ;

        // ---- S = Q K^T (bf16 3-term; accumulators interleaved) ----
        float s[8][4];
        #pragma unroll
        for (int ni = 0; ni < 8; ni++)
            #pragma unroll
            for (int q = 0; q < 4; q++) s[ni][q] = 0.f;

        #pragma unroll
        for (int ks = 0; ks < 4; ks++) {
            unsigned qh[4], ql[4];
            ldsm4(qh, sb + SM_QH + SWZ(aoff + ks * 32));
            ldsm4(ql, sb + SM_QL + SWZ(aoff + ks * 32));
            #pragma unroll
            for (int np = 0; np < 4; np++) {
                unsigned kh[4], kl[4];
                int bo = boff + np * 2048 + ks * 32;
                ldsm4(kh, kvb + SWZ(bo));
                ldsm4(kl, kvb + 8192 + SWZ(bo));
                MMA_BF16(s[2 * np],     qh, kh[0], kh[1]);
                MMA_BF16(s[2 * np + 1], qh, kh[2], kh[3]);
                MMA_BF16(s[2 * np],     ql, kh[0], kh[1]);
                MMA_BF16(s[2 * np + 1], ql, kh[2], kh[3]);
                MMA_BF16(s[2 * np],     qh, kl[0], kl[1]);
                MMA_BF16(s[2 * np + 1], qh, kl[2], kl[3]);
            }
        }

        // ---- bias add ----
        const float* bp0 = biass + (kv0 + 127 - wrow - gid);
        #pragma unroll
        for (int ni = 0; ni < 8; ni++) {
            int c = ni * 8 + 2 * tig;
            s[ni][0] += bp0[c];
            s[ni][1] += bp0[c + 1];
            s[ni][2] += bp0[c - 8];
            s[ni][3] += bp0[c - 7];
        }

        // ---- online softmax (magic exp2; m-register stores ROUNDED max mn') ----
        float mx0 = -1e30f, mx1 = -1e30f;
        #pragma unroll
        for (int ni = 0; ni < 8; ni++) {
            mx0 = fmaxf(mx0, fmaxf(s[ni][0], s[ni][1]));
            mx1 = fmaxf(mx1, fmaxf(s[ni][2], s[ni][3]));
        }
        mx0 = fmaxf(mx0, __shfl_xor_sync(0xffffffffu, mx0, 1));
        mx0 = fmaxf(mx0, __shfl_xor_sync(0xffffffffu, mx0, 2));
        mx1 = fmaxf(mx1, __shfl_xor_sync(0xffffffffu, mx1, 1));
        mx1 = fmaxf(mx1, __shfl_xor_sync(0xffffffffu, mx1, 2));
        float mn0 = fmaxf(m0r, mx0), mn1 = fmaxf(m1r, mx1);
        float Cm0 = MAGIC - mn0, Cm1 = MAGIC - mn1;
        float a0 = exp2m(m0r, Cm0), a1 = exp2m(m1r, Cm1);
        m0r = MAGIC - Cm0;   // mn0' (integer) — keeps all tiles' normalizers consistent
        m1r = MAGIC - Cm1;   // mn1'

        #pragma unroll
        for (int ni = 0; ni < 8; ni++) {
            s[ni][0] = exp2m(s[ni][0], Cm0);
            s[ni][1] = exp2m(s[ni][1], Cm0);
            s[ni][2] = exp2m(s[ni][2], Cm1);
            s[ni][3] = exp2m(s[ni][3], Cm1);
        }

        #pragma unroll
        for (int ni = 0; ni < 8; ni++) {
            o[ni][0] *= a0; o[ni][1] *= a0;
            o[ni][2] *= a1; o[ni][3] *= a1;
        }

        // ---- O += P V (fp16 P, single fp16 V); l via ones-MMA ----
        float lacc[4] = {0.f, 0.f, 0.f, 0.f};
        #pragma unroll
        for (int kk = 0; kk < 4; kk++) {
            unsigned pa[4];
            pa[0] = pkh(s[2 * kk][0],     s[2 * kk][1]);
            pa[1] = pkh(s[2 * kk][2],     s[2 * kk][3]);
            pa[2] = pkh(s[2 * kk + 1][0], s[2 * kk + 1][1]);
            pa[3] = pkh(s[2 * kk + 1][2], s[2 * kk + 1][3]);
            MMA_F16(lacc, pa, ONES16, ONES16);
            #pragma unroll
            for (int np = 0; np < 4; np++) {
                unsigned vh[4];
                int vo = voff4 + kk * 2048 + np * 32;
                ldsm4t(vh, kvb + 16384 + SWZ(vo));
                MMA_F16(o[2 * np],     pa, vh[0], vh[1]);
                MMA_F16(o[2 * np + 1], pa, vh[2], vh[3]);
            }
        }
        l0r = l0r * a0 + lacc[0];
        l1r = l1r * a1 + lacc[2];
    }

    // epilogue: O -> bf16 hi/lo planes
    float inv0 = 1.f / l0r, inv1 = 1.f / l1r;
    size_t orow0 = (size_t)(b * N_TOK + q0 + wrow + gid) * DKV + h * 64;
    #pragma unroll
    for (int ni = 0; ni < 8; ni++) {
        int c = ni * 8 + 2 * tig;
        st_pair(g_OH, g_OL, orow0 + c,           o[ni][0] * inv0, o[ni][1] * inv0);
        st_pair(g_OH, g_OL, orow0 + 8 * DKV + c, o[ni][2] * inv1, o[ni][3] * inv1);
    }
}

// ---------------- launch ----------------
extern "C" void kernel_launch(void* const* d_in, const int* in_sizes, int n_in,
                              void* d_out, int out_size) {
    const float* hs = (const float*)d_in[0];
    const float* Wq = (const float*)d_in[1];
    const float* Wk = (const float*)d_in[2];
    const float* Wv = (const float*)d_in[3];
    const float* Wo = (const float*)d_in[4];
    const float* rb = (const float*)d_in[5];
    float* out = (float*)d_out;

    void *phsH, *phsL, *pWfH, *pWfL, *pWoH, *pWoL, *pOH, *pOL;
    cudaGetSymbolAddress(&phsH, g_hsH);
    cudaGetSymbolAddress(&phsL, g_hsL);
    cudaGetSymbolAddress(&pWfH, g_WfH);
    cudaGetSymbolAddress(&pWfL, g_WfL);
    cudaGetSymbolAddress(&pWoH, g_WoH);
    cudaGetSymbolAddress(&pWoL, g_WoL);
    cudaGetSymbolAddress(&pOH, g_OH);
    cudaGetSymbolAddress(&pOL, g_OL);

    fold_kernel<<<1024, 256>>>(Wq, Wk, Wv, Wo, rb);                       // 0
    hsplit_kernel<<<8192, 256>>>(hs);                                     // 1

    cudaFuncSetAttribute(gemm_bf16p, cudaFuncAttributeMaxDynamicSharedMemorySize, GSM_TOT);
    gemm_bf16p<<<dim3(768 / GBN, M_TOTAL / GBM), 256, GSM_TOT>>>(         // 2: proj
        (const __nv_bfloat16*)phsH, (const __nv_bfloat16*)phsL,
        (const __nv_bfloat16*)pWfH, (const __nv_bfloat16*)pWfL,
        nullptr, M_TOTAL, 768, DM, 1);

    cudaFuncSetAttribute(attn_mma, cudaFuncAttributeMaxDynamicSharedMemorySize, SM_TOT);
    attn_mma<<<dim3(N_TOK / QT, BATCH * 4), 256, SM_TOT>>>();             // 3

    gemm_bf16p<<<dim3(DM / GBN, M_TOTAL / GBM), 256, GSM_TOT>>>(          // 4: out
        (const __nv_bfloat16*)pOH, (const __nv_bfloat16*)pOL,
        (const __nv_bfloat16*)pWoH, (const __nv_bfloat16*)pWoL,
        out, M_TOTAL, DM, DKV, 0);
}